// round 5
// baseline (speedup 1.0000x reference)
#include <cuda_runtime.h>
#include <stdint.h>

#define HH 128
#define WW 160
#define HWSZ (HH * WW)          // 20480
#define BMAX 4
#define FLOW_SCALE 160.0f

#define TBITS 20
#define TSIZE (1u << TBITS)
#define TMASK (TSIZE - 1u)
__device__ uint32_t g_hash[(size_t)BMAX * TSIZE];         // 16 MB, L2-resident
// Packed accumulator: low 32 = event count, high 32 = distinct-src count.
__device__ unsigned long long g_acc[BMAX * 2 * HWSZ];     // 1.25 MB

#define BLOCKS_PER_BATCH 37
#define EV_THREADS 1024
#define SMEM_BYTES (HWSZ * (int)sizeof(float2))           // 160 KB

// ---------------------------------------------------------------------------
// Zero hash + acc.
// ---------------------------------------------------------------------------
__global__ void prep_kernel() {
    size_t tid  = (size_t)blockIdx.x * blockDim.x + threadIdx.x;
    size_t nthr = (size_t)gridDim.x * blockDim.x;

    uint4* hm = reinterpret_cast<uint4*>(g_hash);
    size_t n4 = ((size_t)BMAX * TSIZE) / 4;
    uint4 z4 = make_uint4(0u, 0u, 0u, 0u);
    for (size_t i = tid; i < n4; i += nthr) hm[i] = z4;

    ulonglong2* am = reinterpret_cast<ulonglong2*>(g_acc);
    size_t na = ((size_t)BMAX * 2 * HWSZ) / 2;
    for (size_t i = tid; i < na; i += nthr) am[i] = make_ulonglong2(0ull, 0ull);
}

// ---------------------------------------------------------------------------
// Per-event: flow lookup from SMEM, warp, round, hash dedup, fused u64 add.
// One block per (batch, event-slice); flow for the batch staged in smem.
// ---------------------------------------------------------------------------
__global__ void __launch_bounds__(EV_THREADS, 1)
event_kernel(const float* __restrict__ flow,
             const float4* __restrict__ events,
             int N) {
    extern __shared__ float2 s_flow[];   // 20480 entries (fx, fy)

    int b     = blockIdx.x / BLOCKS_PER_BATCH;
    int slice = blockIdx.x % BLOCKS_PER_BATCH;

    // Stage this batch's flow into smem, interleaved (coalesced gmem reads).
    const float* fb = flow + (size_t)b * 2 * HWSZ;
    for (int j = threadIdx.x; j < HWSZ; j += EV_THREADS)
        s_flow[j] = make_float2(fb[j], fb[HWSZ + j]);
    __syncthreads();

    // Event slice for this block.
    int per   = (N + BLOCKS_PER_BATCH - 1) / BLOCKS_PER_BATCH;
    int start = slice * per;
    int end   = start + per; if (end > N) end = N;

    const float4* ev = events + (size_t)b * N;
    uint32_t* tbl = g_hash + ((size_t)b << TBITS);
    unsigned long long* accb = g_acc + (size_t)b * 2 * HWSZ;

    for (int i = start + threadIdx.x; i < end; i += EV_THREADS) {
        float4 e = ev[i];               // (t, y, x, p)
        float t = e.x, y = e.y, x = e.z, p = e.w;

        int src = (int)(__fadd_rn(__fmul_rn(y, (float)WW), x));

        float2 f = s_flow[src];         // (fx, fy) from smem

        // warped = yx + (1-t) * flow * 160   (exact ref op order, no FMA)
        float s  = __fadd_rn(1.0f, -t);
        float wy = __fadd_rn(y, __fmul_rn(__fmul_rn(s, f.y), FLOW_SCALE));
        float wx = __fadd_rn(x, __fmul_rn(__fmul_rn(s, f.x), FLOW_SCALE));

        // jnp.round == round half to even == rintf
        float ry = rintf(wy);
        float rx = rintf(wx);

        if (!(ry >= 0.0f && ry < (float)HH && rx >= 0.0f && rx < (float)WW))
            continue;

        int fw = (int)ry * WW + (int)rx;
        int c  = (p > 0.0f) ? 0 : 1;

        // hash dedup: direct CAS (slots go 0 -> tag exactly once)
        uint32_t key = ((uint32_t)c << 30) | ((uint32_t)src << 15) | (uint32_t)fw;
        uint32_t tag = key + 1u;
        uint32_t h   = (key * 2654435761u) >> (32 - TBITS);

        unsigned long long inc = 1ull;
        while (true) {
            uint32_t old = atomicCAS(&tbl[h], 0u, tag);
            if (old == 0u) { inc = 0x100000001ull; break; }  // first occurrence
            if (old == tag) break;                           // duplicate
            h = (h + 1u) & TMASK;
        }

        atomicAdd(&accb[(size_t)c * HWSZ + fw], inc);
    }
}

// ---------------------------------------------------------------------------
// Final: out = contrib>0 ? cnt/contrib : 0
// ---------------------------------------------------------------------------
__global__ void div_kernel(float* __restrict__ out, int n) {
    int i = blockIdx.x * blockDim.x + threadIdx.x;
    if (i >= n) return;
    unsigned long long v = g_acc[i];
    uint32_t cnt = (uint32_t)v;
    uint32_t ctb = (uint32_t)(v >> 32);
    out[i] = (ctb > 0u) ? ((float)cnt / (float)ctb) : 0.0f;
}

extern "C" void kernel_launch(void* const* d_in, const int* in_sizes, int n_in,
                              void* d_out, int out_size) {
    const float*  flow   = (const float*)d_in[0];   // (B, 2, H, W)
    const float4* events = (const float4*)d_in[1];  // (B, N, 4)
    float* out = (float*)d_out;                     // (B, 2, H, W)

    int B = in_sizes[0] / (2 * HWSZ);
    if (B > BMAX) B = BMAX;
    int N = in_sizes[1] / (4 * B);

    static int smem_set = -1;
    if (smem_set < 0) {
        cudaFuncSetAttribute(event_kernel,
                             cudaFuncAttributeMaxDynamicSharedMemorySize,
                             SMEM_BYTES);
        smem_set = 1;
    }

    prep_kernel<<<4096, 256>>>();

    event_kernel<<<B * BLOCKS_PER_BATCH, EV_THREADS, SMEM_BYTES>>>(flow, events, N);

    int dn = B * 2 * HWSZ;
    div_kernel<<<(dn + 255) / 256, 256>>>(out, dn);
}

// round 6
// speedup vs baseline: 1.0643x; 1.0643x over previous
#include <cuda_runtime.h>
#include <stdint.h>

#define HH 128
#define WW 160
#define HWSZ (HH * WW)          // 20480
#define BMAX 4
#define FLOW_SCALE 160.0f

#define TBITS 20
#define TSIZE (1u << TBITS)
#define TMASK (TSIZE - 1u)
__device__ uint32_t g_hash[(size_t)BMAX * TSIZE];         // 16 MB, L2-resident
// Packed accumulator: low 32 = event count, high 32 = distinct-src count.
__device__ unsigned long long g_acc[BMAX * 2 * HWSZ];     // 1.25 MB
__device__ float2   g_flow2[BMAX * HWSZ];                 // interleaved (fx, fy)

#define EPT 4
#define EV_THREADS 256

// ---------------------------------------------------------------------------
// Zero hash + acc, build interleaved flow.
// ---------------------------------------------------------------------------
__global__ void prep_kernel(const float* __restrict__ flow, int B) {
    size_t tid  = (size_t)blockIdx.x * blockDim.x + threadIdx.x;
    size_t nthr = (size_t)gridDim.x * blockDim.x;

    uint4* hm = reinterpret_cast<uint4*>(g_hash);
    const size_t n4 = ((size_t)BMAX * TSIZE) / 4;        // 1,048,576
    uint4 z4 = make_uint4(0u, 0u, 0u, 0u);
    for (size_t i = tid; i < n4; i += nthr) hm[i] = z4;

    ulonglong2* am = reinterpret_cast<ulonglong2*>(g_acc);
    const size_t na = ((size_t)BMAX * 2 * HWSZ) / 2;     // 81,920
    for (size_t i = tid; i < na; i += nthr) am[i] = make_ulonglong2(0ull, 0ull);

    size_t nflow = (size_t)B * HWSZ;
    for (size_t i = tid; i < nflow; i += nthr) {
        size_t b = i >> 15;              // HWSZ = 20480 < 32768; use div-free split
        size_t j = i - b * HWSZ;
        b = i / HWSZ; j = i % HWSZ;      // (compiler folds; HWSZ is constant)
        const float* fb = flow + b * 2 * HWSZ;
        g_flow2[i] = make_float2(fb[j], fb[HWSZ + j]);   // (fx, fy)
    }
}

// ---------------------------------------------------------------------------
// Per-event pipeline, 4 events per thread with batched load phases.
// gridDim.y = batch index (no integer division in the hot path).
// ---------------------------------------------------------------------------
__global__ void __launch_bounds__(EV_THREADS)
event_kernel(const float4* __restrict__ events, int N) {
    const int b = blockIdx.y;
    const int base = blockIdx.x * (EV_THREADS * EPT) + threadIdx.x;

    const float4* ev = events + (size_t)b * N;
    const float2* fl = g_flow2 + (size_t)b * HWSZ;
    uint32_t* tbl = g_hash + ((size_t)b << TBITS);
    unsigned long long* accb = g_acc + (size_t)b * 2 * HWSZ;

    // Phase 1: batched event loads (independent LDG.128s)
    float4 e[EPT];
    bool   ok[EPT];
#pragma unroll
    for (int k = 0; k < EPT; k++) {
        int i = base + k * EV_THREADS;
        ok[k] = (i < N);
        if (ok[k]) e[k] = ev[i];
    }

    // Phase 2: src + batched flow gathers (independent LDG.64s)
    int    src[EPT];
    float2 f[EPT];
#pragma unroll
    for (int k = 0; k < EPT; k++) {
        if (!ok[k]) continue;
        src[k] = (int)(__fadd_rn(__fmul_rn(e[k].y, (float)WW), e[k].z));
        f[k] = __ldg(&fl[src[k]]);
    }

    // Phase 3: warp + round + dedup + fused accumulate
#pragma unroll
    for (int k = 0; k < EPT; k++) {
        if (!ok[k]) continue;
        float t = e[k].x, y = e[k].y, x = e[k].z, p = e[k].w;

        // warped = yx + (1-t)*flow*160 (exact ref op order, no FMA)
        float s  = __fadd_rn(1.0f, -t);
        float wy = __fadd_rn(y, __fmul_rn(__fmul_rn(s, f[k].y), FLOW_SCALE));
        float wx = __fadd_rn(x, __fmul_rn(__fmul_rn(s, f[k].x), FLOW_SCALE));

        float ry = rintf(wy);            // jnp.round == half-to-even
        float rx = rintf(wx);

        if (!(ry >= 0.0f && ry < (float)HH && rx >= 0.0f && rx < (float)WW))
            continue;

        int fw = (int)ry * WW + (int)rx;
        int c  = (p > 0.0f) ? 0 : 1;

        uint32_t key = ((uint32_t)c << 30) | ((uint32_t)src[k] << 15) | (uint32_t)fw;
        uint32_t tag = key + 1u;
        uint32_t h   = (key * 2654435761u) >> (32 - TBITS);

        unsigned long long inc = 1ull;
        while (true) {
            uint32_t old = atomicCAS(&tbl[h], 0u, tag);
            if (old == 0u) { inc = 0x100000001ull; break; } // first occurrence
            if (old == tag) break;                          // duplicate
            h = (h + 1u) & TMASK;
        }

        atomicAdd(&accb[(size_t)c * HWSZ + fw], inc);       // fire-and-forget RED
    }
}

// ---------------------------------------------------------------------------
// Final: out = contrib>0 ? cnt/contrib : 0
// ---------------------------------------------------------------------------
__global__ void div_kernel(float* __restrict__ out, int n) {
    int i = blockIdx.x * blockDim.x + threadIdx.x;
    if (i >= n) return;
    unsigned long long v = g_acc[i];
    uint32_t cnt = (uint32_t)v;
    uint32_t ctb = (uint32_t)(v >> 32);
    out[i] = (ctb > 0u) ? ((float)cnt / (float)ctb) : 0.0f;
}

extern "C" void kernel_launch(void* const* d_in, const int* in_sizes, int n_in,
                              void* d_out, int out_size) {
    const float*  flow   = (const float*)d_in[0];   // (B, 2, H, W)
    const float4* events = (const float4*)d_in[1];  // (B, N, 4)
    float* out = (float*)d_out;                     // (B, 2, H, W)

    int B = in_sizes[0] / (2 * HWSZ);
    if (B > BMAX) B = BMAX;
    int N = in_sizes[1] / (4 * B);

    prep_kernel<<<8192, 256>>>(flow, B);

    dim3 grid((N + EV_THREADS * EPT - 1) / (EV_THREADS * EPT), B);
    event_kernel<<<grid, EV_THREADS>>>(events, N);

    int dn = B * 2 * HWSZ;
    div_kernel<<<(dn + 255) / 256, 256>>>(out, dn);
}

// round 7
// speedup vs baseline: 1.2654x; 1.1890x over previous
#include <cuda_runtime.h>
#include <stdint.h>

#define HH 128
#define WW 160
#define HWSZ (HH * WW)          // 20480
#define BMAX 4
#define FLOW_SCALE 160.0f

#define TBITS 20
#define TSIZE (1u << TBITS)
#define TMASK (TSIZE - 1u)
__device__ uint32_t g_hash[(size_t)BMAX * TSIZE];         // 16 MB, L2-resident
// Packed accumulator: low 32 = event count, high 32 = distinct-src count.
__device__ unsigned long long g_acc[BMAX * 2 * HWSZ];     // 1.25 MB
__device__ float2   g_flow2[BMAX * HWSZ];                 // interleaved (fx, fy)

// ---------------------------------------------------------------------------
// Zero hash + acc, build interleaved flow (identical to R4).
// ---------------------------------------------------------------------------
__global__ void prep_kernel(const float* __restrict__ flow, int B) {
    size_t tid  = (size_t)blockIdx.x * blockDim.x + threadIdx.x;
    size_t nthr = (size_t)gridDim.x * blockDim.x;

    uint4* hm = reinterpret_cast<uint4*>(g_hash);
    const size_t n4 = ((size_t)BMAX * TSIZE) / 4;
    uint4 z4 = make_uint4(0u, 0u, 0u, 0u);
    for (size_t i = tid; i < n4; i += nthr) hm[i] = z4;

    ulonglong2* am = reinterpret_cast<ulonglong2*>(g_acc);
    const size_t na = ((size_t)BMAX * 2 * HWSZ) / 2;
    for (size_t i = tid; i < na; i += nthr) am[i] = make_ulonglong2(0ull, 0ull);

    size_t nflow = (size_t)B * HWSZ;
    for (size_t i = tid; i < nflow; i += nthr) {
        size_t b = i / HWSZ, j = i % HWSZ;
        const float* fb = flow + b * 2 * HWSZ;
        g_flow2[i] = make_float2(fb[j], fb[HWSZ + j]);  // (fx, fy)
    }
}

// ---------------------------------------------------------------------------
// Per-event: R4 body, but batch = blockIdx.y (no i/N division; L1-friendly
// per-batch flow locality).
// ---------------------------------------------------------------------------
__global__ void __launch_bounds__(256)
event_kernel(const float4* __restrict__ events, int N) {
    const int b = blockIdx.y;
    const int base = (blockIdx.x * blockDim.x + threadIdx.x) * 2;

    const float4* ev = events + (size_t)b * N;
    const float2* fl = g_flow2 + (size_t)b * HWSZ;
    uint32_t* tbl = g_hash + ((size_t)b << TBITS);
    unsigned long long* accb = g_acc + (size_t)b * 2 * HWSZ;

#pragma unroll
    for (int k = 0; k < 2; k++) {
        int i = base + k;
        if (i >= N) return;

        float4 e = ev[i];               // (t, y, x, p)
        float t = e.x, y = e.y, x = e.z, p = e.w;

        int src = (int)(__fadd_rn(__fmul_rn(y, (float)WW), x));

        float2 f = __ldg(&fl[src]);     // (fx, fy)

        // warped = yx + (1-t) * flow * 160  (exact ref op order, no FMA)
        float s  = __fadd_rn(1.0f, -t);
        float wy = __fadd_rn(y, __fmul_rn(__fmul_rn(s, f.y), FLOW_SCALE));
        float wx = __fadd_rn(x, __fmul_rn(__fmul_rn(s, f.x), FLOW_SCALE));

        // jnp.round == round half to even == rintf
        float ry = rintf(wy);
        float rx = rintf(wx);

        if (!(ry >= 0.0f && ry < (float)HH && rx >= 0.0f && rx < (float)WW))
            continue;

        int fw = (int)ry * WW + (int)rx;
        int c  = (p > 0.0f) ? 0 : 1;

        // hash dedup: direct CAS (slots go 0 -> tag exactly once)
        uint32_t key = ((uint32_t)c << 30) | ((uint32_t)src << 15) | (uint32_t)fw;
        uint32_t tag = key + 1u;
        uint32_t h   = (key * 2654435761u) >> (32 - TBITS);

        unsigned long long inc = 1ull;
        while (true) {
            uint32_t old = atomicCAS(&tbl[h], 0u, tag);
            if (old == 0u) { inc = 0x100000001ull; break; }  // first occurrence
            if (old == tag) break;                           // duplicate
            h = (h + 1u) & TMASK;
        }

        atomicAdd(&accb[(size_t)c * HWSZ + fw], inc);
    }
}

// ---------------------------------------------------------------------------
// Final: out = contrib>0 ? cnt/contrib : 0
// ---------------------------------------------------------------------------
__global__ void div_kernel(float* __restrict__ out, int n) {
    int i = blockIdx.x * blockDim.x + threadIdx.x;
    if (i >= n) return;
    unsigned long long v = g_acc[i];
    uint32_t cnt = (uint32_t)v;
    uint32_t ctb = (uint32_t)(v >> 32);
    out[i] = (ctb > 0u) ? ((float)cnt / (float)ctb) : 0.0f;
}

extern "C" void kernel_launch(void* const* d_in, const int* in_sizes, int n_in,
                              void* d_out, int out_size) {
    const float*  flow   = (const float*)d_in[0];   // (B, 2, H, W)
    const float4* events = (const float4*)d_in[1];  // (B, N, 4)
    float* out = (float*)d_out;                     // (B, 2, H, W)

    int B = in_sizes[0] / (2 * HWSZ);
    if (B > BMAX) B = BMAX;
    int N = in_sizes[1] / (4 * B);

    prep_kernel<<<4096, 256>>>(flow, B);

    dim3 grid((N + 511) / 512, B);
    event_kernel<<<grid, 256>>>(events, N);

    int dn = B * 2 * HWSZ;
    div_kernel<<<(dn + 255) / 256, 256>>>(out, dn);
}

// round 8
// speedup vs baseline: 1.2714x; 1.0048x over previous
#include <cuda_runtime.h>
#include <stdint.h>

#define HH 128
#define WW 160
#define HWSZ (HH * WW)          // 20480
#define BMAX 4
#define FLOW_SCALE 160.0f

#define TBITS 20
#define TSIZE (1u << TBITS)
#define TMASK (TSIZE - 1u)
__device__ uint32_t g_hash[(size_t)BMAX * TSIZE];         // 16 MB, L2-resident
// Packed accumulator: low 32 = event count, high 32 = distinct-src count.
__device__ unsigned long long g_acc[BMAX * 2 * HWSZ];     // 1.25 MB
__device__ float2   g_flow2[BMAX * HWSZ];                 // interleaved (fx, fy)

// ---------------------------------------------------------------------------
// Zero hash + acc, build interleaved flow (identical to R4).
// ---------------------------------------------------------------------------
__global__ void prep_kernel(const float* __restrict__ flow, int B) {
    size_t tid  = (size_t)blockIdx.x * blockDim.x + threadIdx.x;
    size_t nthr = (size_t)gridDim.x * blockDim.x;

    uint4* hm = reinterpret_cast<uint4*>(g_hash);
    const size_t n4 = ((size_t)BMAX * TSIZE) / 4;
    uint4 z4 = make_uint4(0u, 0u, 0u, 0u);
    for (size_t i = tid; i < n4; i += nthr) hm[i] = z4;

    ulonglong2* am = reinterpret_cast<ulonglong2*>(g_acc);
    const size_t na = ((size_t)BMAX * 2 * HWSZ) / 2;
    for (size_t i = tid; i < na; i += nthr) am[i] = make_ulonglong2(0ull, 0ull);

    size_t nflow = (size_t)B * HWSZ;
    for (size_t i = tid; i < nflow; i += nthr) {
        size_t b = i / HWSZ, j = i % HWSZ;
        const float* fb = flow + b * 2 * HWSZ;
        g_flow2[i] = make_float2(fb[j], fb[HWSZ + j]);  // (fx, fy)
    }
}

// ---------------------------------------------------------------------------
// Per-event: R4 body, but batch = blockIdx.y (no i/N division; L1-friendly
// per-batch flow locality).
// ---------------------------------------------------------------------------
__global__ void __launch_bounds__(256)
event_kernel(const float4* __restrict__ events, int N) {
    const int b = blockIdx.y;
    const int base = (blockIdx.x * blockDim.x + threadIdx.x) * 2;

    const float4* ev = events + (size_t)b * N;
    const float2* fl = g_flow2 + (size_t)b * HWSZ;
    uint32_t* tbl = g_hash + ((size_t)b << TBITS);
    unsigned long long* accb = g_acc + (size_t)b * 2 * HWSZ;

#pragma unroll
    for (int k = 0; k < 2; k++) {
        int i = base + k;
        if (i >= N) return;

        float4 e = ev[i];               // (t, y, x, p)
        float t = e.x, y = e.y, x = e.z, p = e.w;

        int src = (int)(__fadd_rn(__fmul_rn(y, (float)WW), x));

        float2 f = __ldg(&fl[src]);     // (fx, fy)

        // warped = yx + (1-t) * flow * 160  (exact ref op order, no FMA)
        float s  = __fadd_rn(1.0f, -t);
        float wy = __fadd_rn(y, __fmul_rn(__fmul_rn(s, f.y), FLOW_SCALE));
        float wx = __fadd_rn(x, __fmul_rn(__fmul_rn(s, f.x), FLOW_SCALE));

        // jnp.round == round half to even == rintf
        float ry = rintf(wy);
        float rx = rintf(wx);

        if (!(ry >= 0.0f && ry < (float)HH && rx >= 0.0f && rx < (float)WW))
            continue;

        int fw = (int)ry * WW + (int)rx;
        int c  = (p > 0.0f) ? 0 : 1;

        // hash dedup: direct CAS (slots go 0 -> tag exactly once)
        uint32_t key = ((uint32_t)c << 30) | ((uint32_t)src << 15) | (uint32_t)fw;
        uint32_t tag = key + 1u;
        uint32_t h   = (key * 2654435761u) >> (32 - TBITS);

        unsigned long long inc = 1ull;
        while (true) {
            uint32_t old = atomicCAS(&tbl[h], 0u, tag);
            if (old == 0u) { inc = 0x100000001ull; break; }  // first occurrence
            if (old == tag) break;                           // duplicate
            h = (h + 1u) & TMASK;
        }

        atomicAdd(&accb[(size_t)c * HWSZ + fw], inc);
    }
}

// ---------------------------------------------------------------------------
// Final: out = contrib>0 ? cnt/contrib : 0
// ---------------------------------------------------------------------------
__global__ void div_kernel(float* __restrict__ out, int n) {
    int i = blockIdx.x * blockDim.x + threadIdx.x;
    if (i >= n) return;
    unsigned long long v = g_acc[i];
    uint32_t cnt = (uint32_t)v;
    uint32_t ctb = (uint32_t)(v >> 32);
    out[i] = (ctb > 0u) ? ((float)cnt / (float)ctb) : 0.0f;
}

extern "C" void kernel_launch(void* const* d_in, const int* in_sizes, int n_in,
                              void* d_out, int out_size) {
    const float*  flow   = (const float*)d_in[0];   // (B, 2, H, W)
    const float4* events = (const float4*)d_in[1];  // (B, N, 4)
    float* out = (float*)d_out;                     // (B, 2, H, W)

    int B = in_sizes[0] / (2 * HWSZ);
    if (B > BMAX) B = BMAX;
    int N = in_sizes[1] / (4 * B);

    prep_kernel<<<4096, 256>>>(flow, B);

    dim3 grid((N + 511) / 512, B);
    event_kernel<<<grid, 256>>>(events, N);

    int dn = B * 2 * HWSZ;
    div_kernel<<<(dn + 255) / 256, 256>>>(out, dn);
}